// round 6
// baseline (speedup 1.0000x reference)
#include <cuda_runtime.h>
#include <math.h>

#define DISP 3
#define CH   256
#define HH   56
#define WW   56
#define WS2  49
#define XP   36      // pitch for xs / MsT / PsT (floats): row-indexed frags conflict-free
#define SP   40      // pitch for ss: column-indexed B-frags conflict-free

__device__ float g_MT[1024];  // transposed, tf32-rounded: MT[d][c] = (Wq^T Wk / sqrt32)[c][d]
__device__ float g_PT[1024];  // transposed, tf32-rounded: PT[d][c] = (Wv^T Wl^T)[c][d]

__device__ __forceinline__ float tf32r(float x) {
    unsigned u; asm("cvt.rna.tf32.f32 %0, %1;" : "=r"(u) : "f"(x));
    return __uint_as_float(u);
}
__device__ __forceinline__ unsigned tf32u(float x) {
    unsigned u; asm("cvt.rna.tf32.f32 %0, %1;" : "=r"(u) : "f"(x));
    return u;
}

__device__ __forceinline__ void mma_tf32(float& c0, float& c1, float& c2, float& c3,
                                         unsigned a0, unsigned a1, unsigned a2, unsigned a3,
                                         unsigned b0, unsigned b1) {
    asm volatile("mma.sync.aligned.m16n8k8.row.col.f32.tf32.tf32.f32 "
        "{%0,%1,%2,%3}, {%4,%5,%6,%7}, {%8,%9}, {%0,%1,%2,%3};"
        : "+f"(c0), "+f"(c1), "+f"(c2), "+f"(c3)
        : "r"(a0), "r"(a1), "r"(a2), "r"(a3), "r"(b0), "r"(b1));
}

// Convert a 16x8 C-tile (c0..c3) to the A-fragment of the same 8-col block.
// C: lane(lr,lc) holds cols 2lc,2lc+1 at rows lr,lr+8.
// A: lane(lr,lc) needs cols lc, lc+4 at rows lr,lr+8.
__device__ __forceinline__ void c2a(float c0, float c1, float c2, float c3, int lane, int lc,
                                    unsigned& a0, unsigned& a1, unsigned& a2, unsigned& a3) {
    int src0 = (lane & 28) | (lc >> 1);
    int src2 = src0 + 2;
    bool odd = lc & 1;
    float v0 = __shfl_sync(0xffffffffu, c0, src0);
    float v1 = __shfl_sync(0xffffffffu, c1, src0);
    float w0 = __shfl_sync(0xffffffffu, c2, src0);
    float w1 = __shfl_sync(0xffffffffu, c3, src0);
    a0 = tf32u(odd ? v1 : v0);
    a1 = tf32u(odd ? w1 : w0);
    v0 = __shfl_sync(0xffffffffu, c0, src2);
    v1 = __shfl_sync(0xffffffffu, c1, src2);
    w0 = __shfl_sync(0xffffffffu, c2, src2);
    w1 = __shfl_sync(0xffffffffu, c3, src2);
    a2 = tf32u(odd ? v1 : v0);
    a3 = tf32u(odd ? w1 : w0);
}

__global__ void precompute_kernel(const float* __restrict__ Wq,
                                  const float* __restrict__ Wk,
                                  const float* __restrict__ Wv,
                                  const float* __restrict__ Wl) {
    int i = threadIdx.x;          // 0..1023
    int c = i >> 5, d = i & 31;
    float m = 0.f, p = 0.f;
#pragma unroll
    for (int j = 0; j < 32; ++j) {
        m += Wq[j * 32 + c] * Wk[j * 32 + d];   // (Wq^T Wk)[c][d]
        p += Wv[j * 32 + c] * Wl[d * 32 + j];   // (Wv^T Wl^T)[c][d]
    }
    g_MT[d * 32 + c] = tf32r(m * 0.17677669529663687f);
    g_PT[d * 32 + c] = tf32r(p);
}

__global__ __launch_bounds__(128, 6)
void swca_kernel(const float* __restrict__ x, const float* __restrict__ skip,
                 const float* __restrict__ pe, float* __restrict__ out) {
    const int win   = blockIdx.x;   // 0..63
    const int head  = blockIdx.y;
    const int batch = blockIdx.z;
    const int nh = win >> 3, nw = win & 7;
    const int tid  = threadIdx.x;
    const int lane = tid & 31, warp = tid >> 5;
    const int lr = lane >> 2, lc = lane & 3;
    const int m0 = warp * 16;

    __shared__ __align__(16) float xs[64 * XP];
    __shared__ __align__(16) float ss[64 * SP];
    __shared__ __align__(16) float Ms[32 * XP];   // MT rows d=0..31
    __shared__ __align__(16) float Ps[32 * XP];   // PT rows d=0..31
    __shared__ float pes[169];
    __shared__ int   srow[WS2];

    for (int i = tid; i < 169; i += 128) pes[i] = pe[i];
    // vectorized copy of pre-transposed M/P into pitched smem
    for (int i = tid; i < 512; i += 128) {
        int which = i >> 8;               // 0 = M, 1 = P
        int r  = (i >> 3) & 31;
        int c4 = (i & 7) << 2;
        float4 v = *(const float4*)((which ? g_PT : g_MT) + r * 32 + c4);
        *(float4*)((which ? Ps : Ms) + r * XP + c4) = v;
    }

    const size_t base = (size_t)batch * (HH * WW) * CH + head * 32;

    // ---- gather (rows 49..63 zero-padded), tf32-round once
    for (int idx = tid; idx < 512; idx += 128) {
        int t = idx >> 3, c4 = (idx & 7) << 2;
        float4 xv = make_float4(0.f, 0.f, 0.f, 0.f);
        float4 sv = xv;
        if (t < WS2) {
            int wi = t / 7, wj = t - wi * 7;
            int r  = nh * 7 + wi + DISP;  if (r  >= HH) r  -= HH;
            int cc = nw * 7 + wj + DISP;  if (cc >= WW) cc -= WW;
            int sr = r * WW + cc;
            if (c4 == 0) srow[t] = sr;
            size_t g = base + (size_t)sr * CH + c4;
            xv = *(const float4*)(x + g);
            sv = *(const float4*)(skip + g);
        }
        xv.x = tf32r(xv.x); xv.y = tf32r(xv.y); xv.z = tf32r(xv.z); xv.w = tf32r(xv.w);
        sv.x = tf32r(sv.x); sv.y = tf32r(sv.y); sv.z = tf32r(sv.z); sv.w = tf32r(sv.w);
        *(float4*)&xs[t * XP + c4] = xv;
        *(float4*)&ss[t * SP + c4] = sv;
    }
    __syncthreads();   // the ONLY block-wide barrier

    // ======== qm = xs @ M  (C-frags -> register shuffle -> A-frags qa) ========
    unsigned qa[4][4];
    {
        unsigned xa[4][4];
#pragma unroll
        for (int kt = 0; kt < 4; ++kt) {
            int k0 = kt * 8;
            xa[kt][0] = __float_as_uint(xs[(m0 + lr)     * XP + k0 + lc]);
            xa[kt][1] = __float_as_uint(xs[(m0 + lr + 8) * XP + k0 + lc]);
            xa[kt][2] = __float_as_uint(xs[(m0 + lr)     * XP + k0 + lc + 4]);
            xa[kt][3] = __float_as_uint(xs[(m0 + lr + 8) * XP + k0 + lc + 4]);
        }
#pragma unroll
        for (int nt = 0; nt < 4; ++nt) {
            float c0 = 0.f, c1 = 0.f, c2 = 0.f, c3 = 0.f;
#pragma unroll
            for (int kt = 0; kt < 4; ++kt) {
                unsigned b0 = __float_as_uint(Ms[(nt * 8 + lr) * XP + kt * 8 + lc]);
                unsigned b1 = __float_as_uint(Ms[(nt * 8 + lr) * XP + kt * 8 + lc + 4]);
                mma_tf32(c0, c1, c2, c3, xa[kt][0], xa[kt][1], xa[kt][2], xa[kt][3], b0, b1);
            }
            c2a(c0, c1, c2, c3, lane, lc, qa[nt][0], qa[nt][1], qa[nt][2], qa[nt][3]);
        }
    }

    // ======== scores = qm @ xs^T ========
    float sc[7][4];
#pragma unroll
    for (int nt = 0; nt < 7; ++nt) {
        float c0 = 0.f, c1 = 0.f, c2 = 0.f, c3 = 0.f;
#pragma unroll
        for (int kt = 0; kt < 4; ++kt) {
            unsigned b0 = __float_as_uint(xs[(nt * 8 + lr) * XP + kt * 8 + lc]);
            unsigned b1 = __float_as_uint(xs[(nt * 8 + lr) * XP + kt * 8 + lc + 4]);
            mma_tf32(c0, c1, c2, c3, qa[kt][0], qa[kt][1], qa[kt][2], qa[kt][3], b0, b1);
        }
        sc[nt][0] = c0; sc[nt][1] = c1; sc[nt][2] = c2; sc[nt][3] = c3;
    }

    // ======== bias + mask + softmax (register-resident, deferred normalization) ========
    const bool mrow = (nh == 7), mcol = (nw == 7);
    const float NEG = -1e30f;
    const int r0 = m0 + lr, r1 = r0 + 8;
    float inv0, inv1;
    {
        int rq0 = r0 < 49 ? r0 : 48, rq1 = r1 < 49 ? r1 : 48;
        int qi0 = rq0 / 7, qj0 = rq0 - qi0 * 7;
        int qi1 = rq1 / 7, qj1 = rq1 - qi1 * 7;
        int qo0 = (6 - qi0) * 13 + (6 - qj0);
        int qo1 = (6 - qi1) * 13 + (6 - qj1);
        bool q0i = qi0 >= 4, q0j = qj0 >= 4, q1i = qi1 >= 4, q1j = qj1 >= 4;

        float mx0 = NEG, mx1 = NEG;
#pragma unroll
        for (int nt = 0; nt < 7; ++nt) {
#pragma unroll
            for (int j = 0; j < 2; ++j) {
                int col = nt * 8 + 2 * lc + j;
                bool valid = col < 49;
                int colc = valid ? col : 0;
                int ki = colc / 7, kj = colc - ki * 7;
                int kidx = ki * 13 + kj;
                bool ki4 = ki >= 4, kj4 = kj >= 4;
                bool dead0 = !valid || (mrow && (ki4 != q0i)) || (mcol && (kj4 != q0j));
                bool dead1 = !valid || (mrow && (ki4 != q1i)) || (mcol && (kj4 != q1j));
                float s0 = dead0 ? NEG : sc[nt][j]     + pes[kidx + qo0];
                float s1 = dead1 ? NEG : sc[nt][2 + j] + pes[kidx + qo1];
                sc[nt][j] = s0; sc[nt][2 + j] = s1;
                mx0 = fmaxf(mx0, s0); mx1 = fmaxf(mx1, s1);
            }
        }
        mx0 = fmaxf(mx0, __shfl_xor_sync(0xffffffffu, mx0, 1));
        mx0 = fmaxf(mx0, __shfl_xor_sync(0xffffffffu, mx0, 2));
        mx1 = fmaxf(mx1, __shfl_xor_sync(0xffffffffu, mx1, 1));
        mx1 = fmaxf(mx1, __shfl_xor_sync(0xffffffffu, mx1, 2));
        float sm0 = 0.f, sm1 = 0.f;
#pragma unroll
        for (int nt = 0; nt < 7; ++nt) {
#pragma unroll
            for (int j = 0; j < 2; ++j) {
                float p0 = __expf(sc[nt][j]     - mx0);
                float p1 = __expf(sc[nt][2 + j] - mx1);
                sc[nt][j] = p0; sc[nt][2 + j] = p1;
                sm0 += p0; sm1 += p1;
            }
        }
        sm0 += __shfl_xor_sync(0xffffffffu, sm0, 1);
        sm0 += __shfl_xor_sync(0xffffffffu, sm0, 2);
        sm1 += __shfl_xor_sync(0xffffffffu, sm1, 1);
        sm1 += __shfl_xor_sync(0xffffffffu, sm1, 2);
        inv0 = __fdividef(1.f, sm0);
        inv1 = __fdividef(1.f, sm1);
    }

    // ======== probs C-frags -> A-frags (register shuffle) ========
    unsigned aa[7][4];
#pragma unroll
    for (int t = 0; t < 7; ++t)
        c2a(sc[t][0], sc[t][1], sc[t][2], sc[t][3], lane, lc,
            aa[t][0], aa[t][1], aa[t][2], aa[t][3]);

    // ======== T = probs @ ss  (ss read row-major directly as B: B[n=d][k=token]) ========
    unsigned ta[4][4];
#pragma unroll
    for (int nt = 0; nt < 4; ++nt) {
        float c0 = 0.f, c1 = 0.f, c2 = 0.f, c3 = 0.f;
#pragma unroll
        for (int kt = 0; kt < 7; ++kt) {
            unsigned b0 = __float_as_uint(ss[(kt * 8 + lc)     * SP + nt * 8 + lr]);
            unsigned b1 = __float_as_uint(ss[(kt * 8 + lc + 4) * SP + nt * 8 + lr]);
            mma_tf32(c0, c1, c2, c3, aa[kt][0], aa[kt][1], aa[kt][2], aa[kt][3], b0, b1);
        }
        c2a(c0, c1, c2, c3, lane, lc, ta[nt][0], ta[nt][1], ta[nt][2], ta[nt][3]);
    }

    // ======== out = T @ P, scale rows by 1/sum, write ========
    {
        bool w0 = r0 < WS2, w1 = r1 < WS2;
        size_t g0 = w0 ? base + (size_t)srow[r0] * CH : 0;
        size_t g1 = w1 ? base + (size_t)srow[r1] * CH : 0;
#pragma unroll
        for (int nt = 0; nt < 4; ++nt) {
            float c0 = 0.f, c1 = 0.f, c2 = 0.f, c3 = 0.f;
#pragma unroll
            for (int kt = 0; kt < 4; ++kt) {
                unsigned b0 = __float_as_uint(Ps[(nt * 8 + lr) * XP + kt * 8 + lc]);
                unsigned b1 = __float_as_uint(Ps[(nt * 8 + lr) * XP + kt * 8 + lc + 4]);
                mma_tf32(c0, c1, c2, c3, ta[kt][0], ta[kt][1], ta[kt][2], ta[kt][3], b0, b1);
            }
            int col = nt * 8 + 2 * lc;
            if (w0) *(float2*)(out + g0 + col) = make_float2(c0 * inv0, c1 * inv0);
            if (w1) *(float2*)(out + g1 + col) = make_float2(c2 * inv1, c3 * inv1);
        }
    }
}

extern "C" void kernel_launch(void* const* d_in, const int* in_sizes, int n_in,
                              void* d_out, int out_size) {
    const float* skip = (const float*)d_in[0];
    const float* x    = (const float*)d_in[1];
    const float* Wq   = (const float*)d_in[2];
    const float* Wk   = (const float*)d_in[3];
    const float* Wv   = (const float*)d_in[4];
    const float* Wl   = (const float*)d_in[5];
    const float* pe   = (const float*)d_in[6];
    (void)in_sizes; (void)n_in; (void)out_size;

    precompute_kernel<<<1, 1024>>>(Wq, Wk, Wv, Wl);
    dim3 grid(64, 8, 16);
    swca_kernel<<<grid, 128>>>(x, skip, pe, (float*)d_out);
}

// round 7
// speedup vs baseline: 2.4850x; 2.4850x over previous
#include <cuda_runtime.h>
#include <cuda_fp16.h>
#include <math.h>

#define DISP 3
#define CH   256
#define HH   56
#define WW   56
#define WS2  49
#define XRP  40    // xr pitch (halves): row-major x, conflict-free for half2 frags
#define MTP  40    // MT/PT pitch (halves)
#define SSTP 72    // ssT pitch (halves): [d][token]

__device__ __half g_MT[1024];  // MT[n=d_out][k=c_in] = (Wq^T Wk / sqrt32)[c][d]
__device__ __half g_PT[1024];  // PT[n=d_out][k=c_in] = (Wv^T Wl^T)[c][d]

__device__ __forceinline__ unsigned pack_h2(float lo, float hi) {
    unsigned u;
    asm("cvt.rn.f16x2.f32 %0, %1, %2;" : "=r"(u) : "f"(hi), "f"(lo));
    return u;
}

__device__ __forceinline__ void mma_f16(float& c0, float& c1, float& c2, float& c3,
                                        unsigned a0, unsigned a1, unsigned a2, unsigned a3,
                                        unsigned b0, unsigned b1) {
    asm volatile("mma.sync.aligned.m16n8k16.row.col.f32.f16.f16.f32 "
        "{%0,%1,%2,%3}, {%4,%5,%6,%7}, {%8,%9}, {%0,%1,%2,%3};"
        : "+f"(c0), "+f"(c1), "+f"(c2), "+f"(c3)
        : "r"(a0), "r"(a1), "r"(a2), "r"(a3), "r"(b0), "r"(b1));
}

__global__ void precompute_kernel(const float* __restrict__ Wq,
                                  const float* __restrict__ Wk,
                                  const float* __restrict__ Wv,
                                  const float* __restrict__ Wl) {
    int i = blockIdx.x * 128 + threadIdx.x;   // 0..1023
    int c = i >> 5, d = i & 31;
    float m = 0.f, p = 0.f;
#pragma unroll
    for (int j = 0; j < 32; ++j) {
        m += Wq[j * 32 + c] * Wk[j * 32 + d];   // (Wq^T Wk)[c][d]
        p += Wv[j * 32 + c] * Wl[d * 32 + j];   // (Wv^T Wl^T)[c][d]
    }
    g_MT[d * 32 + c] = __float2half_rn(m * 0.17677669529663687f);
    g_PT[d * 32 + c] = __float2half_rn(p);
}

__global__ __launch_bounds__(128, 8)
void swca_kernel(const float* __restrict__ x, const float* __restrict__ skip,
                 const float* __restrict__ pe, float* __restrict__ out) {
    const int win   = blockIdx.x;   // 0..63
    const int head  = blockIdx.y;
    const int batch = blockIdx.z;
    const int nh = win >> 3, nw = win & 7;
    const int tid  = threadIdx.x;
    const int lane = tid & 31, warp = tid >> 5;
    const int lr = lane >> 2, lc = lane & 3;   // group row g / tid-in-group t
    const int m0 = warp * 16;

    __shared__ __align__(16) __half xr[64 * XRP];    // x tile row-major [token][d]
    __shared__ __align__(16) __half ssT[32 * SSTP];  // skip tile transposed [d][token]
    __shared__ __align__(16) __half Ms[32 * MTP];    // MT pitched
    __shared__ __align__(16) __half Ps[32 * MTP];    // PT pitched
    __shared__ float pes[169];
    __shared__ int   srow[WS2];

    for (int i = tid; i < 169; i += 128) pes[i] = pe[i];
    {   // copy pre-transposed M/P (half) into pitched smem: 1 LDG.128 + 1 STS.128 each
        int r = tid >> 2, ch = (tid & 3) << 3;
        *(uint4*)&Ms[r * MTP + ch] = *(const uint4*)&g_MT[r * 32 + ch];
        *(uint4*)&Ps[r * MTP + ch] = *(const uint4*)&g_PT[r * 32 + ch];
    }

    const size_t base = (size_t)batch * (HH * WW) * CH + head * 32;

    // ---- gather: xr row-major half, ssT transposed half (rows/cols >=49 zeroed)
    for (int idx = tid; idx < 512; idx += 128) {
        int t = idx >> 3, c4 = (idx & 7) << 2;
        float4 xv = make_float4(0.f, 0.f, 0.f, 0.f);
        float4 sv = xv;
        if (t < WS2) {
            int wi = t / 7, wj = t - wi * 7;
            int r  = nh * 7 + wi + DISP;  if (r  >= HH) r  -= HH;
            int cc = nw * 7 + wj + DISP;  if (cc >= WW) cc -= WW;
            int sr = r * WW + cc;
            if (c4 == 0) srow[t] = sr;
            size_t g = base + (size_t)sr * CH + c4;
            xv = *(const float4*)(x + g);
            sv = *(const float4*)(skip + g);
        }
        uint2 xp = make_uint2(pack_h2(xv.x, xv.y), pack_h2(xv.z, xv.w));
        *(uint2*)&xr[t * XRP + c4] = xp;
        ssT[(c4 + 0) * SSTP + t] = __float2half_rn(sv.x);
        ssT[(c4 + 1) * SSTP + t] = __float2half_rn(sv.y);
        ssT[(c4 + 2) * SSTP + t] = __float2half_rn(sv.z);
        ssT[(c4 + 3) * SSTP + t] = __float2half_rn(sv.w);
    }
    __syncthreads();   // the only block-wide barrier

    // ======== qm = x @ M  (A from xr, B from Ms; C packs straight into A-frags) ========
    unsigned qa[2][4];
    {
        unsigned xa[2][4];
#pragma unroll
        for (int kk = 0; kk < 2; ++kk) {
            int k0 = kk * 16 + 2 * lc;
            xa[kk][0] = *(const unsigned*)&xr[(m0 + lr)     * XRP + k0];
            xa[kk][1] = *(const unsigned*)&xr[(m0 + lr + 8) * XRP + k0];
            xa[kk][2] = *(const unsigned*)&xr[(m0 + lr)     * XRP + k0 + 8];
            xa[kk][3] = *(const unsigned*)&xr[(m0 + lr + 8) * XRP + k0 + 8];
        }
        float qc[4][4];
#pragma unroll
        for (int nt = 0; nt < 4; ++nt) {
            float c0 = 0.f, c1 = 0.f, c2 = 0.f, c3 = 0.f;
#pragma unroll
            for (int kk = 0; kk < 2; ++kk) {
                int k0 = kk * 16 + 2 * lc;
                unsigned b0 = *(const unsigned*)&Ms[(nt * 8 + lr) * MTP + k0];
                unsigned b1 = *(const unsigned*)&Ms[(nt * 8 + lr) * MTP + k0 + 8];
                mma_f16(c0, c1, c2, c3, xa[kk][0], xa[kk][1], xa[kk][2], xa[kk][3], b0, b1);
            }
            qc[nt][0] = c0; qc[nt][1] = c1; qc[nt][2] = c2; qc[nt][3] = c3;
        }
#pragma unroll
        for (int kk = 0; kk < 2; ++kk) {
            qa[kk][0] = pack_h2(qc[2 * kk][0],     qc[2 * kk][1]);
            qa[kk][1] = pack_h2(qc[2 * kk][2],     qc[2 * kk][3]);
            qa[kk][2] = pack_h2(qc[2 * kk + 1][0], qc[2 * kk + 1][1]);
            qa[kk][3] = pack_h2(qc[2 * kk + 1][2], qc[2 * kk + 1][3]);
        }
    }

    // ======== scores = qm @ x^T  (B = xr row-major: b0 = x[token][2t,2t+1]) ========
    float sc[7][4];
#pragma unroll
    for (int nt = 0; nt < 7; ++nt) {
        float c0 = 0.f, c1 = 0.f, c2 = 0.f, c3 = 0.f;
#pragma unroll
        for (int kk = 0; kk < 2; ++kk) {
            int k0 = kk * 16 + 2 * lc;
            unsigned b0 = *(const unsigned*)&xr[(nt * 8 + lr) * XRP + k0];
            unsigned b1 = *(const unsigned*)&xr[(nt * 8 + lr) * XRP + k0 + 8];
            mma_f16(c0, c1, c2, c3, qa[kk][0], qa[kk][1], qa[kk][2], qa[kk][3], b0, b1);
        }
        sc[nt][0] = c0; sc[nt][1] = c1; sc[nt][2] = c2; sc[nt][3] = c3;
    }

    // ======== bias + mask + softmax (register resident, deferred normalization) ========
    const bool mrow = (nh == 7), mcol = (nw == 7);
    const float NEG = -1e30f;
    const int r0 = m0 + lr, r1 = r0 + 8;
    float inv0, inv1;
    {
        int rq0 = r0 < 49 ? r0 : 48, rq1 = r1 < 49 ? r1 : 48;
        int qi0 = rq0 / 7, qj0 = rq0 - qi0 * 7;
        int qi1 = rq1 / 7, qj1 = rq1 - qi1 * 7;
        int qo0 = (6 - qi0) * 13 + (6 - qj0);
        int qo1 = (6 - qi1) * 13 + (6 - qj1);
        bool q0i = qi0 >= 4, q0j = qj0 >= 4, q1i = qi1 >= 4, q1j = qj1 >= 4;

        float mx0 = NEG, mx1 = NEG;
#pragma unroll
        for (int nt = 0; nt < 7; ++nt) {
#pragma unroll
            for (int j = 0; j < 2; ++j) {
                int col = nt * 8 + 2 * lc + j;
                bool valid = col < 49;
                int colc = valid ? col : 0;
                int ki = colc / 7, kj = colc - ki * 7;
                int kidx = ki * 13 + kj;
                bool ki4 = ki >= 4, kj4 = kj >= 4;
                bool dead0 = !valid || (mrow && (ki4 != q0i)) || (mcol && (kj4 != q0j));
                bool dead1 = !valid || (mrow && (ki4 != q1i)) || (mcol && (kj4 != q1j));
                float s0 = dead0 ? NEG : sc[nt][j]     + pes[kidx + qo0];
                float s1 = dead1 ? NEG : sc[nt][2 + j] + pes[kidx + qo1];
                sc[nt][j] = s0; sc[nt][2 + j] = s1;
                mx0 = fmaxf(mx0, s0); mx1 = fmaxf(mx1, s1);
            }
        }
        mx0 = fmaxf(mx0, __shfl_xor_sync(0xffffffffu, mx0, 1));
        mx0 = fmaxf(mx0, __shfl_xor_sync(0xffffffffu, mx0, 2));
        mx1 = fmaxf(mx1, __shfl_xor_sync(0xffffffffu, mx1, 1));
        mx1 = fmaxf(mx1, __shfl_xor_sync(0xffffffffu, mx1, 2));
        float sm0 = 0.f, sm1 = 0.f;
#pragma unroll
        for (int nt = 0; nt < 7; ++nt) {
#pragma unroll
            for (int j = 0; j < 2; ++j) {
                float p0 = __expf(sc[nt][j]     - mx0);
                float p1 = __expf(sc[nt][2 + j] - mx1);
                sc[nt][j] = p0; sc[nt][2 + j] = p1;
                sm0 += p0; sm1 += p1;
            }
        }
        sm0 += __shfl_xor_sync(0xffffffffu, sm0, 1);
        sm0 += __shfl_xor_sync(0xffffffffu, sm0, 2);
        sm1 += __shfl_xor_sync(0xffffffffu, sm1, 1);
        sm1 += __shfl_xor_sync(0xffffffffu, sm1, 2);
        inv0 = __fdividef(1.f, sm0);
        inv1 = __fdividef(1.f, sm1);
    }

    // ======== probs C-frags -> A-frags via f16x2 packs (token k-dim, 64 padded) ========
    unsigned aa[4][4];
#pragma unroll
    for (int kk = 0; kk < 3; ++kk) {
        aa[kk][0] = pack_h2(sc[2 * kk][0],     sc[2 * kk][1]);
        aa[kk][1] = pack_h2(sc[2 * kk][2],     sc[2 * kk][3]);
        aa[kk][2] = pack_h2(sc[2 * kk + 1][0], sc[2 * kk + 1][1]);
        aa[kk][3] = pack_h2(sc[2 * kk + 1][2], sc[2 * kk + 1][3]);
    }
    aa[3][0] = pack_h2(sc[6][0], sc[6][1]);
    aa[3][1] = pack_h2(sc[6][2], sc[6][3]);
    aa[3][2] = 0u;
    aa[3][3] = 0u;

    // ======== T = probs @ skip_v  (B = ssT: b0 = ssT[d][2t,2t+1] contiguous) ========
    unsigned ta[2][4];
    {
        float tc[4][4];
#pragma unroll
        for (int nt = 0; nt < 4; ++nt) {
            float c0 = 0.f, c1 = 0.f, c2 = 0.f, c3 = 0.f;
#pragma unroll
            for (int kt = 0; kt < 4; ++kt) {
                int k0 = kt * 16 + 2 * lc;
                unsigned b0 = *(const unsigned*)&ssT[(nt * 8 + lr) * SSTP + k0];
                unsigned b1 = *(const unsigned*)&ssT[(nt * 8 + lr) * SSTP + k0 + 8];
                mma_f16(c0, c1, c2, c3, aa[kt][0], aa[kt][1], aa[kt][2], aa[kt][3], b0, b1);
            }
            tc[nt][0] = c0; tc[nt][1] = c1; tc[nt][2] = c2; tc[nt][3] = c3;
        }
#pragma unroll
        for (int kk = 0; kk < 2; ++kk) {
            ta[kk][0] = pack_h2(tc[2 * kk][0],     tc[2 * kk][1]);
            ta[kk][1] = pack_h2(tc[2 * kk][2],     tc[2 * kk][3]);
            ta[kk][2] = pack_h2(tc[2 * kk + 1][0], tc[2 * kk + 1][1]);
            ta[kk][3] = pack_h2(tc[2 * kk + 1][2], tc[2 * kk + 1][3]);
        }
    }

    // ======== out = T @ P, scale rows by 1/sum, write ========
    {
        bool w0 = r0 < WS2, w1 = r1 < WS2;
        size_t g0 = w0 ? base + (size_t)srow[r0] * CH : 0;
        size_t g1 = w1 ? base + (size_t)srow[r1] * CH : 0;
#pragma unroll
        for (int nt = 0; nt < 4; ++nt) {
            float c0 = 0.f, c1 = 0.f, c2 = 0.f, c3 = 0.f;
#pragma unroll
            for (int kk = 0; kk < 2; ++kk) {
                int k0 = kk * 16 + 2 * lc;
                unsigned b0 = *(const unsigned*)&Ps[(nt * 8 + lr) * MTP + k0];
                unsigned b1 = *(const unsigned*)&Ps[(nt * 8 + lr) * MTP + k0 + 8];
                mma_f16(c0, c1, c2, c3, ta[kk][0], ta[kk][1], ta[kk][2], ta[kk][3], b0, b1);
            }
            int col = nt * 8 + 2 * lc;
            if (w0) *(float2*)(out + g0 + col) = make_float2(c0 * inv0, c1 * inv0);
            if (w1) *(float2*)(out + g1 + col) = make_float2(c2 * inv1, c3 * inv1);
        }
    }
}

extern "C" void kernel_launch(void* const* d_in, const int* in_sizes, int n_in,
                              void* d_out, int out_size) {
    const float* skip = (const float*)d_in[0];
    const float* x    = (const float*)d_in[1];
    const float* Wq   = (const float*)d_in[2];
    const float* Wk   = (const float*)d_in[3];
    const float* Wv   = (const float*)d_in[4];
    const float* Wl   = (const float*)d_in[5];
    const float* pe   = (const float*)d_in[6];
    (void)in_sizes; (void)n_in; (void)out_size;

    precompute_kernel<<<8, 128>>>(Wq, Wk, Wv, Wl);
    dim3 grid(64, 8, 16);
    swca_kernel<<<grid, 128>>>(x, skip, pe, (float*)d_out);
}

// round 8
// speedup vs baseline: 2.5801x; 1.0383x over previous
#include <cuda_runtime.h>
#include <cuda_fp16.h>
#include <math.h>

#define DISP 3
#define CH   256
#define HH   56
#define WW   56
#define WS2  49
#define XRP  40    // xr pitch (halves) — 80B row stride, LDSM conflict-free
#define SSP  40    // ss pitch (halves), row-major now
#define MTP  40    // MT/PT pitch (halves)

__device__ __half g_MT[1024];  // MT[n=d_out][k=c_in] = (Wq^T Wk / sqrt32)[c][d]
__device__ __half g_PT[1024];  // PT[n=d_out][k=c_in] = (Wv^T Wl^T)[c][d]

__device__ __forceinline__ unsigned pack_h2(float lo, float hi) {
    unsigned u;
    asm("cvt.rn.f16x2.f32 %0, %1, %2;" : "=r"(u) : "f"(hi), "f"(lo));
    return u;
}

__device__ __forceinline__ void mma_f16(float& c0, float& c1, float& c2, float& c3,
                                        unsigned a0, unsigned a1, unsigned a2, unsigned a3,
                                        unsigned b0, unsigned b1) {
    asm volatile("mma.sync.aligned.m16n8k16.row.col.f32.f16.f16.f32 "
        "{%0,%1,%2,%3}, {%4,%5,%6,%7}, {%8,%9}, {%0,%1,%2,%3};"
        : "+f"(c0), "+f"(c1), "+f"(c2), "+f"(c3)
        : "r"(a0), "r"(a1), "r"(a2), "r"(a3), "r"(b0), "r"(b1));
}

__device__ __forceinline__ void ldsm_x4(unsigned addr, unsigned& r0, unsigned& r1,
                                        unsigned& r2, unsigned& r3) {
    asm volatile("ldmatrix.sync.aligned.m8n8.x4.shared.b16 {%0,%1,%2,%3}, [%4];"
        : "=r"(r0), "=r"(r1), "=r"(r2), "=r"(r3) : "r"(addr));
}
__device__ __forceinline__ void ldsm_x4_t(unsigned addr, unsigned& r0, unsigned& r1,
                                          unsigned& r2, unsigned& r3) {
    asm volatile("ldmatrix.sync.aligned.m8n8.x4.trans.shared.b16 {%0,%1,%2,%3}, [%4];"
        : "=r"(r0), "=r"(r1), "=r"(r2), "=r"(r3) : "r"(addr));
}

__global__ void precompute_kernel(const float* __restrict__ Wq,
                                  const float* __restrict__ Wk,
                                  const float* __restrict__ Wv,
                                  const float* __restrict__ Wl) {
    int i = blockIdx.x * 128 + threadIdx.x;   // 0..1023
    int c = i >> 5, d = i & 31;
    float m = 0.f, p = 0.f;
#pragma unroll
    for (int j = 0; j < 32; ++j) {
        m += Wq[j * 32 + c] * Wk[j * 32 + d];   // (Wq^T Wk)[c][d]
        p += Wv[j * 32 + c] * Wl[d * 32 + j];   // (Wv^T Wl^T)[c][d]
    }
    g_MT[d * 32 + c] = __float2half_rn(m * 0.17677669529663687f);
    g_PT[d * 32 + c] = __float2half_rn(p);
}

__global__ __launch_bounds__(128, 8)
void swca_kernel(const float* __restrict__ x, const float* __restrict__ skip,
                 const float* __restrict__ pe, float* __restrict__ out) {
    const int win   = blockIdx.x;   // 0..63
    const int head  = blockIdx.y;
    const int batch = blockIdx.z;
    const int nh = win >> 3, nw = win & 7;
    const int tid  = threadIdx.x;
    const int lane = tid & 31, warp = tid >> 5;
    const int lr = lane >> 2, lc = lane & 3;   // groupID g / tid-in-group t
    const int m0 = warp * 16;

    __shared__ __align__(16) __half xr[64 * XRP];   // x tile row-major [token][d]
    __shared__ __align__(16) __half ss[64 * SSP];   // skip tile row-major [token][d]
    __shared__ __align__(16) __half Ms[32 * MTP];   // MT pitched [n][k]
    __shared__ __align__(16) __half Ps[32 * MTP];   // PT pitched [n][k]
    __shared__ float pes[169];
    __shared__ int   srow[WS2];

    for (int i = tid; i < 169; i += 128) pes[i] = pe[i];
    {   // copy pre-transposed M/P (half): 1 LDG.128 + 1 STS.128 each
        int r = tid >> 2, ch = (tid & 3) << 3;
        *(uint4*)&Ms[r * MTP + ch] = *(const uint4*)&g_MT[r * 32 + ch];
        *(uint4*)&Ps[r * MTP + ch] = *(const uint4*)&g_PT[r * 32 + ch];
    }

    const size_t base = (size_t)batch * (HH * WW) * CH + head * 32;

    // ---- gather: both tiles row-major half (rows >= 49 zeroed)
    for (int idx = tid; idx < 512; idx += 128) {
        int t = idx >> 3, c4 = (idx & 7) << 2;
        float4 xv = make_float4(0.f, 0.f, 0.f, 0.f);
        float4 sv = xv;
        if (t < WS2) {
            int wi = t / 7, wj = t - wi * 7;
            int r  = nh * 7 + wi + DISP;  if (r  >= HH) r  -= HH;
            int cc = nw * 7 + wj + DISP;  if (cc >= WW) cc -= WW;
            int sr = r * WW + cc;
            if (c4 == 0) srow[t] = sr;
            size_t g = base + (size_t)sr * CH + c4;
            xv = *(const float4*)(x + g);
            sv = *(const float4*)(skip + g);
        }
        *(uint2*)&xr[t * XRP + c4] = make_uint2(pack_h2(xv.x, xv.y), pack_h2(xv.z, xv.w));
        *(uint2*)&ss[t * SSP + c4] = make_uint2(pack_h2(sv.x, sv.y), pack_h2(sv.z, sv.w));
    }
    __syncthreads();   // the only block-wide barrier

    // ---- LDSM lane-address bases (half-element offsets; byte = 2x)
    const int l7 = lane & 7, lh = lane >> 3;            // tile row / tile index
    // B-pattern (xr/Ms/Ps): tile i = k-half i; row = tb + l7, col = lh*8
    const unsigned xrB = (unsigned)__cvta_generic_to_shared(xr) + 2u * (l7 * XRP + lh * 8);
    const unsigned msB = (unsigned)__cvta_generic_to_shared(Ms) + 2u * (l7 * MTP + lh * 8);
    const unsigned psB = (unsigned)__cvta_generic_to_shared(Ps) + 2u * (l7 * MTP + lh * 8);
    // A-pattern (xr): tile i: rowhalf = i&1, khalf = i>>1
    const unsigned xrA = (unsigned)__cvta_generic_to_shared(xr)
                       + 2u * ((m0 + ((lh & 1) << 3) + l7) * XRP + ((lh >> 1) << 3));
    // ss trans pattern: tile i = token-half i; row = tg*32 + lh*8 + l7, col = nt*8
    const unsigned ssT = (unsigned)__cvta_generic_to_shared(ss) + 2u * ((lh * 8 + l7) * SSP);

    // ======== qm = x @ M ========
    unsigned qa[2][4];
    {
        unsigned xa[2][4];
        ldsm_x4(xrA,                xa[0][0], xa[0][1], xa[0][2], xa[0][3]);
        ldsm_x4(xrA + 2u * 16,      xa[1][0], xa[1][1], xa[1][2], xa[1][3]);
        float qc[4][4];
#pragma unroll
        for (int nt = 0; nt < 4; ++nt) {
            unsigned b0, b1, b2, b3;
            ldsm_x4(msB + 2u * (nt * 8 * MTP), b0, b1, b2, b3);
            float c0 = 0.f, c1 = 0.f, c2 = 0.f, c3 = 0.f;
            mma_f16(c0, c1, c2, c3, xa[0][0], xa[0][1], xa[0][2], xa[0][3], b0, b1);
            mma_f16(c0, c1, c2, c3, xa[1][0], xa[1][1], xa[1][2], xa[1][3], b2, b3);
            qc[nt][0] = c0; qc[nt][1] = c1; qc[nt][2] = c2; qc[nt][3] = c3;
        }
#pragma unroll
        for (int kk = 0; kk < 2; ++kk) {
            qa[kk][0] = pack_h2(qc[2 * kk][0],     qc[2 * kk][1]);
            qa[kk][1] = pack_h2(qc[2 * kk][2],     qc[2 * kk][3]);
            qa[kk][2] = pack_h2(qc[2 * kk + 1][0], qc[2 * kk + 1][1]);
            qa[kk][3] = pack_h2(qc[2 * kk + 1][2], qc[2 * kk + 1][3]);
        }
    }

    // ======== scores = qm @ x^T  (B tiles straight from xr rows) ========
    float sc[7][4];
#pragma unroll
    for (int nt = 0; nt < 7; ++nt) {
        unsigned b0, b1, b2, b3;
        ldsm_x4(xrB + 2u * (nt * 8 * XRP), b0, b1, b2, b3);
        float c0 = 0.f, c1 = 0.f, c2 = 0.f, c3 = 0.f;
        mma_f16(c0, c1, c2, c3, qa[0][0], qa[0][1], qa[0][2], qa[0][3], b0, b1);
        mma_f16(c0, c1, c2, c3, qa[1][0], qa[1][1], qa[1][2], qa[1][3], b2, b3);
        sc[nt][0] = c0; sc[nt][1] = c1; sc[nt][2] = c2; sc[nt][3] = c3;
    }

    // ======== bias + mask + softmax (register resident, deferred normalization) ========
    const bool mrow = (nh == 7), mcol = (nw == 7);
    const float NEG = -1e30f;
    const int r0 = m0 + lr, r1 = r0 + 8;
    float inv0, inv1;
    {
        int rq0 = r0 < 49 ? r0 : 48, rq1 = r1 < 49 ? r1 : 48;
        int qi0 = rq0 / 7, qj0 = rq0 - qi0 * 7;
        int qi1 = rq1 / 7, qj1 = rq1 - qi1 * 7;
        int qo0 = (6 - qi0) * 13 + (6 - qj0);
        int qo1 = (6 - qi1) * 13 + (6 - qj1);
        bool q0i = qi0 >= 4, q0j = qj0 >= 4, q1i = qi1 >= 4, q1j = qj1 >= 4;

        float mx0 = NEG, mx1 = NEG;
#pragma unroll
        for (int nt = 0; nt < 7; ++nt) {
#pragma unroll
            for (int j = 0; j < 2; ++j) {
                int col = nt * 8 + 2 * lc + j;
                bool valid = col < 49;
                int colc = valid ? col : 0;
                int ki = colc / 7, kj = colc - ki * 7;
                int kidx = ki * 13 + kj;
                bool ki4 = ki >= 4, kj4 = kj >= 4;
                bool dead0 = !valid || (mrow && (ki4 != q0i)) || (mcol && (kj4 != q0j));
                bool dead1 = !valid || (mrow && (ki4 != q1i)) || (mcol && (kj4 != q1j));
                float s0 = dead0 ? NEG : sc[nt][j]     + pes[kidx + qo0];
                float s1 = dead1 ? NEG : sc[nt][2 + j] + pes[kidx + qo1];
                sc[nt][j] = s0; sc[nt][2 + j] = s1;
                mx0 = fmaxf(mx0, s0); mx1 = fmaxf(mx1, s1);
            }
        }
        mx0 = fmaxf(mx0, __shfl_xor_sync(0xffffffffu, mx0, 1));
        mx0 = fmaxf(mx0, __shfl_xor_sync(0xffffffffu, mx0, 2));
        mx1 = fmaxf(mx1, __shfl_xor_sync(0xffffffffu, mx1, 1));
        mx1 = fmaxf(mx1, __shfl_xor_sync(0xffffffffu, mx1, 2));
        float sm0 = 0.f, sm1 = 0.f;
#pragma unroll
        for (int nt = 0; nt < 7; ++nt) {
#pragma unroll
            for (int j = 0; j < 2; ++j) {
                float p0 = __expf(sc[nt][j]     - mx0);
                float p1 = __expf(sc[nt][2 + j] - mx1);
                sc[nt][j] = p0; sc[nt][2 + j] = p1;
                sm0 += p0; sm1 += p1;
            }
        }
        sm0 += __shfl_xor_sync(0xffffffffu, sm0, 1);
        sm0 += __shfl_xor_sync(0xffffffffu, sm0, 2);
        sm1 += __shfl_xor_sync(0xffffffffu, sm1, 1);
        sm1 += __shfl_xor_sync(0xffffffffu, sm1, 2);
        inv0 = __fdividef(1.f, sm0);
        inv1 = __fdividef(1.f, sm1);
    }

    // ======== probs C-frags -> A-frags via f16x2 packs (k dim = 64 tokens) ========
    unsigned aa[4][4];
#pragma unroll
    for (int kk = 0; kk < 3; ++kk) {
        aa[kk][0] = pack_h2(sc[2 * kk][0],     sc[2 * kk][1]);
        aa[kk][1] = pack_h2(sc[2 * kk][2],     sc[2 * kk][3]);
        aa[kk][2] = pack_h2(sc[2 * kk + 1][0], sc[2 * kk + 1][1]);
        aa[kk][3] = pack_h2(sc[2 * kk + 1][2], sc[2 * kk + 1][3]);
    }
    aa[3][0] = pack_h2(sc[6][0], sc[6][1]);
    aa[3][1] = pack_h2(sc[6][2], sc[6][3]);
    aa[3][2] = 0u;
    aa[3][3] = 0u;

    // ======== T = probs @ skip_v  (B via ldmatrix.trans from row-major ss) ========
    unsigned ta[2][4];
    {
        float tc[4][4];
#pragma unroll
        for (int nt = 0; nt < 4; ++nt) {
            float c0 = 0.f, c1 = 0.f, c2 = 0.f, c3 = 0.f;
#pragma unroll
            for (int tg = 0; tg < 2; ++tg) {   // token groups 0-31 / 32-63
                unsigned b0, b1, b2, b3;
                ldsm_x4_t(ssT + 2u * (tg * 32 * SSP + nt * 8), b0, b1, b2, b3);
                mma_f16(c0, c1, c2, c3,
                        aa[2 * tg][0], aa[2 * tg][1], aa[2 * tg][2], aa[2 * tg][3], b0, b1);
                mma_f16(c0, c1, c2, c3,
                        aa[2 * tg + 1][0], aa[2 * tg + 1][1], aa[2 * tg + 1][2], aa[2 * tg + 1][3], b2, b3);
            }
            tc[nt][0] = c0; tc[nt][1] = c1; tc[nt][2] = c2; tc[nt][3] = c3;
        }
#pragma unroll
        for (int kk = 0; kk < 2; ++kk) {
            ta[kk][0] = pack_h2(tc[2 * kk][0],     tc[2 * kk][1]);
            ta[kk][1] = pack_h2(tc[2 * kk][2],     tc[2 * kk][3]);
            ta[kk][2] = pack_h2(tc[2 * kk + 1][0], tc[2 * kk + 1][1]);
            ta[kk][3] = pack_h2(tc[2 * kk + 1][2], tc[2 * kk + 1][3]);
        }
    }

    // ======== out = T @ P, scale rows by 1/sum, write ========
    {
        bool w0 = r0 < WS2, w1 = r1 < WS2;
        size_t g0 = w0 ? base + (size_t)srow[r0] * CH : 0;
        size_t g1 = w1 ? base + (size_t)srow[r1] * CH : 0;
#pragma unroll
        for (int nt = 0; nt < 4; ++nt) {
            unsigned b0, b1, b2, b3;
            ldsm_x4(psB + 2u * (nt * 8 * MTP), b0, b1, b2, b3);
            float c0 = 0.f, c1 = 0.f, c2 = 0.f, c3 = 0.f;
            mma_f16(c0, c1, c2, c3, ta[0][0], ta[0][1], ta[0][2], ta[0][3], b0, b1);
            mma_f16(c0, c1, c2, c3, ta[1][0], ta[1][1], ta[1][2], ta[1][3], b2, b3);
            int col = nt * 8 + 2 * lc;
            if (w0) *(float2*)(out + g0 + col) = make_float2(c0 * inv0, c1 * inv0);
            if (w1) *(float2*)(out + g1 + col) = make_float2(c2 * inv1, c3 * inv1);
        }
    }
}

extern "C" void kernel_launch(void* const* d_in, const int* in_sizes, int n_in,
                              void* d_out, int out_size) {
    const float* skip = (const float*)d_in[0];
    const float* x    = (const float*)d_in[1];
    const float* Wq   = (const float*)d_in[2];
    const float* Wk   = (const float*)d_in[3];
    const float* Wv   = (const float*)d_in[4];
    const float* Wl   = (const float*)d_in[5];
    const float* pe   = (const float*)d_in[6];
    (void)in_sizes; (void)n_in; (void)out_size;

    precompute_kernel<<<8, 128>>>(Wq, Wk, Wv, Wl);
    dim3 grid(64, 8, 16);
    swca_kernel<<<grid, 128>>>(x, skip, pe, (float*)d_out);
}